// round 7
// baseline (speedup 1.0000x reference)
#include <cuda_runtime.h>

#define D 2048
#define D4 (D / 4)
#define THREADS 512
#define NWARP (THREADS / 32)   // 16

__global__ __launch_bounds__(THREADS, 3) void fc_kernel(
    const float4* __restrict__ feat4, const float4* __restrict__ pos4,
    float4* __restrict__ out4)
{
    __shared__ float sred[9][NWARP];
    __shared__ float salpha[6];

    const int b = blockIdx.x;
    const int t = threadIdx.x;    // 0..511 == float4 index within a feature row
    const long base = (long)b * 3 * D4;

    // ---- load + pos add, register resident ----
    float4 f1 = __ldcs(&feat4[base + 0 * D4 + t]);
    float4 f2 = __ldcs(&feat4[base + 1 * D4 + t]);
    float4 f3 = __ldcs(&feat4[base + 2 * D4 + t]);
    const float4 p0 = __ldg(&pos4[0 * D4 + t]);
    const float4 p1 = __ldg(&pos4[1 * D4 + t]);
    const float4 p2 = __ldg(&pos4[2 * D4 + t]);
    f1.x += p0.x; f1.y += p0.y; f1.z += p0.z; f1.w += p0.w;
    f2.x += p1.x; f2.y += p1.y; f2.z += p1.z; f2.w += p1.w;
    f3.x += p2.x; f3.y += p2.y; f3.z += p2.z; f3.w += p2.w;

    // ---- 9 reductions: |f1|^2 |f2|^2 |f3|^2 f1.f2 f1.f3 f2.f3 sum f1 f2 f3 ----
    float acc[9];
#pragma unroll
    for (int k = 0; k < 9; k++) acc[k] = 0.0f;
    {
        const float ax[4] = {f1.x, f1.y, f1.z, f1.w};
        const float bx[4] = {f2.x, f2.y, f2.z, f2.w};
        const float cx[4] = {f3.x, f3.y, f3.z, f3.w};
#pragma unroll
        for (int k = 0; k < 4; k++) {
            const float fa = ax[k], fb = bx[k], fc = cx[k];
            acc[0] = fmaf(fa, fa, acc[0]);
            acc[1] = fmaf(fb, fb, acc[1]);
            acc[2] = fmaf(fc, fc, acc[2]);
            acc[3] = fmaf(fa, fb, acc[3]);
            acc[4] = fmaf(fa, fc, acc[4]);
            acc[5] = fmaf(fb, fc, acc[5]);
            acc[6] += fa;
            acc[7] += fb;
            acc[8] += fc;
        }
    }

    // warp butterfly reduce
#pragma unroll
    for (int k = 0; k < 9; k++) {
#pragma unroll
        for (int o = 16; o > 0; o >>= 1)
            acc[k] += __shfl_xor_sync(0xffffffffu, acc[k], o);
    }

    const int warp = t >> 5, lane = t & 31;
    if (lane == 0) {
#pragma unroll
        for (int k = 0; k < 9; k++) sred[k][warp] = acc[k];
    }
    __syncthreads();

    // ---- warp 0: parallel cross-warp reduce + alpha epilogue ----
    if (warp == 0) {
        float S[9];
#pragma unroll
        for (int k = 0; k < 9; k++) {
            float v = (lane < NWARP) ? sred[k][lane] : 0.0f;
            v += __shfl_xor_sync(0xffffffffu, v, 8);
            v += __shfl_xor_sync(0xffffffffu, v, 4);
            v += __shfl_xor_sync(0xffffffffu, v, 2);
            v += __shfl_xor_sync(0xffffffffu, v, 1);
            S[k] = __shfl_sync(0xffffffffu, v, 0);
        }
        const float d11 = S[0], d22 = S[1], d33 = S[2];
        const float d12 = S[3], d13 = S[4], d23 = S[5];
        const float s1 = S[6], s2 = S[7], s3 = S[8];

        const float e   = 1e-6f;
        const float De2 = (float)D * 1e-12f;
        // ||a-b+e||^2 = |a|^2+|b|^2-2ab + 2e(sa-sb) + D e^2
        const float q12 = d11 + d22 - 2.0f * d12 + De2;
        const float q13 = d11 + d33 - 2.0f * d13 + De2;
        const float q23 = d22 + d33 - 2.0f * d23 + De2;

        const float t12f = fmaxf(q12 + 2.0f * e * (s1 - s2), 1e-30f);
        const float t12b = fmaxf(q12 + 2.0f * e * (s2 - s1), 1e-30f);
        const float t13f = fmaxf(q13 + 2.0f * e * (s1 - s3), 1e-30f);
        const float t13b = fmaxf(q13 + 2.0f * e * (s3 - s1), 1e-30f);
        const float t23f = fmaxf(q23 + 2.0f * e * (s2 - s3), 1e-30f);
        const float t23b = fmaxf(q23 + 2.0f * e * (s3 - s2), 1e-30f);

        // sqrt(x) = x*rsqrt(x); fast reciprocal divide (validated: rel_err 5e-8)
        const float w12f = __fdividef(1.0f, 1.0f + t12f * rsqrtf(t12f));
        const float w12b = __fdividef(1.0f, 1.0f + t12b * rsqrtf(t12b));
        const float w13f = __fdividef(1.0f, 1.0f + t13f * rsqrtf(t13f));
        const float w13b = __fdividef(1.0f, 1.0f + t13b * rsqrtf(t13b));
        const float w23f = __fdividef(1.0f, 1.0f + t23f * rsqrtf(t23f));
        const float w23b = __fdividef(1.0f, 1.0f + t23b * rsqrtf(t23b));

        const float c12 = 0.5f + 0.5f * d12 * rsqrtf(fmaxf(d11 * d22, 1e-30f));
        const float c13 = 0.5f + 0.5f * d13 * rsqrtf(fmaxf(d11 * d33, 1e-30f));
        const float c23 = 0.5f + 0.5f * d23 * rsqrtf(fmaxf(d22 * d33, 1e-30f));

        if (lane == 0) {
            salpha[0] = w12f + c12;  // o1 coeff on f2
            salpha[1] = w13f + c13;  // o1 coeff on f3
            salpha[2] = w12b + c12;  // o2 coeff on f1
            salpha[3] = w23f + c23;  // o2 coeff on f3
            salpha[4] = w13b + c13;  // o3 coeff on f1
            salpha[5] = w23b + c23;  // o3 coeff on f2
        }
    }
    __syncthreads();

    const float a12 = salpha[0], a13 = salpha[1];
    const float a21 = salpha[2], a23 = salpha[3];
    const float a31 = salpha[4], a32 = salpha[5];

    // ---- store outputs (streaming) ----
    float4 o1, o2, o3;
    o1.x = fmaf(a12, f2.x, fmaf(a13, f3.x, f1.x));
    o1.y = fmaf(a12, f2.y, fmaf(a13, f3.y, f1.y));
    o1.z = fmaf(a12, f2.z, fmaf(a13, f3.z, f1.z));
    o1.w = fmaf(a12, f2.w, fmaf(a13, f3.w, f1.w));
    o2.x = fmaf(a21, f1.x, fmaf(a23, f3.x, f2.x));
    o2.y = fmaf(a21, f1.y, fmaf(a23, f3.y, f2.y));
    o2.z = fmaf(a21, f1.z, fmaf(a23, f3.z, f2.z));
    o2.w = fmaf(a21, f1.w, fmaf(a23, f3.w, f2.w));
    o3.x = fmaf(a31, f1.x, fmaf(a32, f2.x, f3.x));
    o3.y = fmaf(a31, f1.y, fmaf(a32, f2.y, f3.y));
    o3.z = fmaf(a31, f1.z, fmaf(a32, f2.z, f3.z));
    o3.w = fmaf(a31, f1.w, fmaf(a32, f2.w, f3.w));
    __stcs(&out4[base + 0 * D4 + t], o1);
    __stcs(&out4[base + 1 * D4 + t], o2);
    __stcs(&out4[base + 2 * D4 + t], o3);
}

extern "C" void kernel_launch(void* const* d_in, const int* in_sizes, int n_in,
                              void* d_out, int out_size) {
    const float* feat = (const float*)d_in[0];
    const float* pos  = (const float*)d_in[1];
    float* out = (float*)d_out;
    const int B = in_sizes[0] / (3 * D);
    fc_kernel<<<B, THREADS>>>(
        reinterpret_cast<const float4*>(feat),
        reinterpret_cast<const float4*>(pos),
        reinterpret_cast<float4*>(out));
}

// round 8
// speedup vs baseline: 1.0890x; 1.0890x over previous
#include <cuda_runtime.h>

#define D 2048
#define D4 (D / 4)
#define THREADS 256
#define NWARP (THREADS / 32)   // 8
#define NV 2  // float4 chunks per thread per feature: 2048/4/256 = 2

__global__ __launch_bounds__(THREADS, 5) void fc_kernel(
    const float4* __restrict__ feat4, const float4* __restrict__ pos4,
    float4* __restrict__ out4)
{
    __shared__ float sred[6][NWARP];
    __shared__ float salpha[3];

    const int b = blockIdx.x;
    const int t = threadIdx.x;
    const long base = (long)b * 3 * D4;

    // ---- load + pos add, register resident ----
    float4 f1[NV], f2[NV], f3[NV];
#pragma unroll
    for (int v = 0; v < NV; v++) {
        const int i = t + v * THREADS;
        float4 a  = __ldcs(&feat4[base + 0 * D4 + i]);
        float4 bb = __ldcs(&feat4[base + 1 * D4 + i]);
        float4 c  = __ldcs(&feat4[base + 2 * D4 + i]);
        const float4 p0 = __ldg(&pos4[0 * D4 + i]);
        const float4 p1 = __ldg(&pos4[1 * D4 + i]);
        const float4 p2 = __ldg(&pos4[2 * D4 + i]);
        a.x += p0.x; a.y += p0.y; a.z += p0.z; a.w += p0.w;
        bb.x += p1.x; bb.y += p1.y; bb.z += p1.z; bb.w += p1.w;
        c.x += p2.x; c.y += p2.y; c.z += p2.z; c.w += p2.w;
        f1[v] = a; f2[v] = bb; f3[v] = c;
    }

    // ---- 6 reductions: |f1|^2 |f2|^2 |f3|^2 f1.f2 f1.f3 f2.f3 ----
    // (the 1e-6 shift inside the pairwise distance perturbs w by ~3e-8 rel;
    //  dropped — far below the 1e-3 tolerance)
    float acc[6];
#pragma unroll
    for (int k = 0; k < 6; k++) acc[k] = 0.0f;
#pragma unroll
    for (int v = 0; v < NV; v++) {
        const float ax[4] = {f1[v].x, f1[v].y, f1[v].z, f1[v].w};
        const float bx[4] = {f2[v].x, f2[v].y, f2[v].z, f2[v].w};
        const float cx[4] = {f3[v].x, f3[v].y, f3[v].z, f3[v].w};
#pragma unroll
        for (int k = 0; k < 4; k++) {
            const float fa = ax[k], fb = bx[k], fc = cx[k];
            acc[0] = fmaf(fa, fa, acc[0]);
            acc[1] = fmaf(fb, fb, acc[1]);
            acc[2] = fmaf(fc, fc, acc[2]);
            acc[3] = fmaf(fa, fb, acc[3]);
            acc[4] = fmaf(fa, fc, acc[4]);
            acc[5] = fmaf(fb, fc, acc[5]);
        }
    }

    // warp butterfly reduce
#pragma unroll
    for (int k = 0; k < 6; k++) {
#pragma unroll
        for (int o = 16; o > 0; o >>= 1)
            acc[k] += __shfl_xor_sync(0xffffffffu, acc[k], o);
    }

    const int warp = t >> 5, lane = t & 31;
    if (lane == 0) {
#pragma unroll
        for (int k = 0; k < 6; k++) sred[k][warp] = acc[k];
    }
    __syncthreads();

    // ---- warp 0: parallel cross-warp reduce + alpha epilogue ----
    if (warp == 0) {
        float S[6];
#pragma unroll
        for (int k = 0; k < 6; k++) {
            float v = (lane < NWARP) ? sred[k][lane] : 0.0f;
            v += __shfl_xor_sync(0xffffffffu, v, 4);
            v += __shfl_xor_sync(0xffffffffu, v, 2);
            v += __shfl_xor_sync(0xffffffffu, v, 1);
            S[k] = __shfl_sync(0xffffffffu, v, 0);
        }
        const float d11 = S[0], d22 = S[1], d33 = S[2];
        const float d12 = S[3], d13 = S[4], d23 = S[5];

        const float De2 = (float)D * 1e-12f;
        const float q12 = fmaxf(d11 + d22 - 2.0f * d12 + De2, 1e-30f);
        const float q13 = fmaxf(d11 + d33 - 2.0f * d13 + De2, 1e-30f);
        const float q23 = fmaxf(d22 + d33 - 2.0f * d23 + De2, 1e-30f);

        // w = 1/(1+sqrt(q)); sqrt(x) = x*rsqrt(x)
        const float w12 = __fdividef(1.0f, 1.0f + q12 * rsqrtf(q12));
        const float w13 = __fdividef(1.0f, 1.0f + q13 * rsqrtf(q13));
        const float w23 = __fdividef(1.0f, 1.0f + q23 * rsqrtf(q23));

        const float c12 = 0.5f + 0.5f * d12 * rsqrtf(fmaxf(d11 * d22, 1e-30f));
        const float c13 = 0.5f + 0.5f * d13 * rsqrtf(fmaxf(d11 * d33, 1e-30f));
        const float c23 = 0.5f + 0.5f * d23 * rsqrtf(fmaxf(d22 * d33, 1e-30f));

        if (lane == 0) {
            salpha[0] = w12 + c12;  // pair (1,2)
            salpha[1] = w13 + c13;  // pair (1,3)
            salpha[2] = w23 + c23;  // pair (2,3)
        }
    }
    __syncthreads();

    const float a12 = salpha[0], a13 = salpha[1], a23 = salpha[2];

    // ---- store outputs (streaming) ----
#pragma unroll
    for (int v = 0; v < NV; v++) {
        const int i = t + v * THREADS;
        float4 o1, o2, o3;
        o1.x = fmaf(a12, f2[v].x, fmaf(a13, f3[v].x, f1[v].x));
        o1.y = fmaf(a12, f2[v].y, fmaf(a13, f3[v].y, f1[v].y));
        o1.z = fmaf(a12, f2[v].z, fmaf(a13, f3[v].z, f1[v].z));
        o1.w = fmaf(a12, f2[v].w, fmaf(a13, f3[v].w, f1[v].w));
        o2.x = fmaf(a12, f1[v].x, fmaf(a23, f3[v].x, f2[v].x));
        o2.y = fmaf(a12, f1[v].y, fmaf(a23, f3[v].y, f2[v].y));
        o2.z = fmaf(a12, f1[v].z, fmaf(a23, f3[v].z, f2[v].z));
        o2.w = fmaf(a12, f1[v].w, fmaf(a23, f3[v].w, f2[v].w));
        o3.x = fmaf(a13, f1[v].x, fmaf(a23, f2[v].x, f3[v].x));
        o3.y = fmaf(a13, f1[v].y, fmaf(a23, f2[v].y, f3[v].y));
        o3.z = fmaf(a13, f1[v].z, fmaf(a23, f2[v].z, f3[v].z));
        o3.w = fmaf(a13, f1[v].w, fmaf(a23, f2[v].w, f3[v].w));
        __stcs(&out4[base + 0 * D4 + i], o1);
        __stcs(&out4[base + 1 * D4 + i], o2);
        __stcs(&out4[base + 2 * D4 + i], o3);
    }
}

extern "C" void kernel_launch(void* const* d_in, const int* in_sizes, int n_in,
                              void* d_out, int out_size) {
    const float* feat = (const float*)d_in[0];
    const float* pos  = (const float*)d_in[1];
    float* out = (float*)d_out;
    const int B = in_sizes[0] / (3 * D);
    fc_kernel<<<B, THREADS>>>(
        reinterpret_cast<const float4*>(feat),
        reinterpret_cast<const float4*>(pos),
        reinterpret_cast<float4*>(out));
}

// round 9
// speedup vs baseline: 1.1256x; 1.0336x over previous
#include <cuda_runtime.h>

#define D 2048
#define D4 (D / 4)
#define THREADS 256
#define NWARP (THREADS / 32)   // 8
#define NV 2  // float4 chunks per thread per feature: 2048/4/256 = 2

__global__ __launch_bounds__(THREADS, 4) void fc_kernel(
    const float4* __restrict__ feat4, const float4* __restrict__ pos4,
    float4* __restrict__ out4)
{
    __shared__ float sred[6][NWARP];
    __shared__ float salpha[3];

    const int b = blockIdx.x;
    const int t = threadIdx.x;
    const long base = (long)b * 3 * D4;

    // ---- load + pos add, register resident ----
    float4 f1[NV], f2[NV], f3[NV];
#pragma unroll
    for (int v = 0; v < NV; v++) {
        const int i = t + v * THREADS;
        float4 a  = __ldcs(&feat4[base + 0 * D4 + i]);
        float4 bb = __ldcs(&feat4[base + 1 * D4 + i]);
        float4 c  = __ldcs(&feat4[base + 2 * D4 + i]);
        const float4 p0 = __ldg(&pos4[0 * D4 + i]);
        const float4 p1 = __ldg(&pos4[1 * D4 + i]);
        const float4 p2 = __ldg(&pos4[2 * D4 + i]);
        a.x += p0.x; a.y += p0.y; a.z += p0.z; a.w += p0.w;
        bb.x += p1.x; bb.y += p1.y; bb.z += p1.z; bb.w += p1.w;
        c.x += p2.x; c.y += p2.y; c.z += p2.z; c.w += p2.w;
        f1[v] = a; f2[v] = bb; f3[v] = c;
    }

    // ---- 6 reductions: |f1|^2 |f2|^2 |f3|^2 f1.f2 f1.f3 f2.f3 ----
    // (the 1e-6 shift inside the pairwise distance perturbs w by ~3e-8 rel;
    //  dropped — far below the 1e-3 tolerance)
    float acc[6];
#pragma unroll
    for (int k = 0; k < 6; k++) acc[k] = 0.0f;
#pragma unroll
    for (int v = 0; v < NV; v++) {
        const float ax[4] = {f1[v].x, f1[v].y, f1[v].z, f1[v].w};
        const float bx[4] = {f2[v].x, f2[v].y, f2[v].z, f2[v].w};
        const float cx[4] = {f3[v].x, f3[v].y, f3[v].z, f3[v].w};
#pragma unroll
        for (int k = 0; k < 4; k++) {
            const float fa = ax[k], fb = bx[k], fc = cx[k];
            acc[0] = fmaf(fa, fa, acc[0]);
            acc[1] = fmaf(fb, fb, acc[1]);
            acc[2] = fmaf(fc, fc, acc[2]);
            acc[3] = fmaf(fa, fb, acc[3]);
            acc[4] = fmaf(fa, fc, acc[4]);
            acc[5] = fmaf(fb, fc, acc[5]);
        }
    }

    // warp butterfly reduce
#pragma unroll
    for (int k = 0; k < 6; k++) {
#pragma unroll
        for (int o = 16; o > 0; o >>= 1)
            acc[k] += __shfl_xor_sync(0xffffffffu, acc[k], o);
    }

    const int warp = t >> 5, lane = t & 31;
    if (lane == 0) {
#pragma unroll
        for (int k = 0; k < 6; k++) sred[k][warp] = acc[k];
    }
    __syncthreads();

    // ---- warp 0: parallel cross-warp reduce + alpha epilogue ----
    if (warp == 0) {
        float S[6];
#pragma unroll
        for (int k = 0; k < 6; k++) {
            float v = (lane < NWARP) ? sred[k][lane] : 0.0f;
            v += __shfl_xor_sync(0xffffffffu, v, 4);
            v += __shfl_xor_sync(0xffffffffu, v, 2);
            v += __shfl_xor_sync(0xffffffffu, v, 1);
            S[k] = __shfl_sync(0xffffffffu, v, 0);
        }
        const float d11 = S[0], d22 = S[1], d33 = S[2];
        const float d12 = S[3], d13 = S[4], d23 = S[5];

        const float De2 = (float)D * 1e-12f;
        const float q12 = fmaxf(d11 + d22 - 2.0f * d12 + De2, 1e-30f);
        const float q13 = fmaxf(d11 + d33 - 2.0f * d13 + De2, 1e-30f);
        const float q23 = fmaxf(d22 + d33 - 2.0f * d23 + De2, 1e-30f);

        // w = 1/(1+sqrt(q)); sqrt(x) = x*rsqrt(x)
        const float w12 = __fdividef(1.0f, 1.0f + q12 * rsqrtf(q12));
        const float w13 = __fdividef(1.0f, 1.0f + q13 * rsqrtf(q13));
        const float w23 = __fdividef(1.0f, 1.0f + q23 * rsqrtf(q23));

        const float c12 = 0.5f + 0.5f * d12 * rsqrtf(fmaxf(d11 * d22, 1e-30f));
        const float c13 = 0.5f + 0.5f * d13 * rsqrtf(fmaxf(d11 * d33, 1e-30f));
        const float c23 = 0.5f + 0.5f * d23 * rsqrtf(fmaxf(d22 * d33, 1e-30f));

        if (lane == 0) {
            salpha[0] = w12 + c12;  // pair (1,2)
            salpha[1] = w13 + c13;  // pair (1,3)
            salpha[2] = w23 + c23;  // pair (2,3)
        }
    }
    __syncthreads();

    const float a12 = salpha[0], a13 = salpha[1], a23 = salpha[2];

    // ---- store outputs (streaming) ----
#pragma unroll
    for (int v = 0; v < NV; v++) {
        const int i = t + v * THREADS;
        float4 o1, o2, o3;
        o1.x = fmaf(a12, f2[v].x, fmaf(a13, f3[v].x, f1[v].x));
        o1.y = fmaf(a12, f2[v].y, fmaf(a13, f3[v].y, f1[v].y));
        o1.z = fmaf(a12, f2[v].z, fmaf(a13, f3[v].z, f1[v].z));
        o1.w = fmaf(a12, f2[v].w, fmaf(a13, f3[v].w, f1[v].w));
        o2.x = fmaf(a12, f1[v].x, fmaf(a23, f3[v].x, f2[v].x));
        o2.y = fmaf(a12, f1[v].y, fmaf(a23, f3[v].y, f2[v].y));
        o2.z = fmaf(a12, f1[v].z, fmaf(a23, f3[v].z, f2[v].z));
        o2.w = fmaf(a12, f1[v].w, fmaf(a23, f3[v].w, f2[v].w));
        o3.x = fmaf(a13, f1[v].x, fmaf(a23, f2[v].x, f3[v].x));
        o3.y = fmaf(a13, f1[v].y, fmaf(a23, f2[v].y, f3[v].y));
        o3.z = fmaf(a13, f1[v].z, fmaf(a23, f2[v].z, f3[v].z));
        o3.w = fmaf(a13, f1[v].w, fmaf(a23, f2[v].w, f3[v].w));
        __stcs(&out4[base + 0 * D4 + i], o1);
        __stcs(&out4[base + 1 * D4 + i], o2);
        __stcs(&out4[base + 2 * D4 + i], o3);
    }
}

extern "C" void kernel_launch(void* const* d_in, const int* in_sizes, int n_in,
                              void* d_out, int out_size) {
    const float* feat = (const float*)d_in[0];
    const float* pos  = (const float*)d_in[1];
    float* out = (float*)d_out;
    const int B = in_sizes[0] / (3 * D);
    fc_kernel<<<B, THREADS>>>(
        reinterpret_cast<const float4*>(feat),
        reinterpret_cast<const float4*>(pos),
        reinterpret_cast<float4*>(out));
}